// round 5
// baseline (speedup 1.0000x reference)
#include <cuda_runtime.h>
#include <cstdint>

#define N_NODES 50000
#define N_EDGES 800000
#define DIM 128
#define SCAN_NB ((N_NODES + 255) / 256)   // 196 blocks

// Scratch (device globals)
__device__ int   g_cnt[N_NODES];
__device__ int   g_off[N_NODES + 1];
__device__ int   g_cur[N_NODES];
__device__ int   g_bsum[SCAN_NB];
__device__ int   g_boff[SCAN_NB];
__device__ float g_dinv[N_NODES];
__device__ int2  g_edge[N_EDGES];        // {src, norm bits} CSR-by-dst order
__device__ float g_tmp[N_NODES * DIM];
__device__ float g_h[N_NODES * DIM];

// ---------------- degree / CSR build ----------------
__global__ void k_zero_cnt() {
    int i = blockIdx.x * blockDim.x + threadIdx.x;
    if (i < N_NODES) g_cnt[i] = 0;
}

__global__ void k_hist(const int* __restrict__ ei) {
    int e = blockIdx.x * blockDim.x + threadIdx.x;
    if (e < N_EDGES) atomicAdd(&g_cnt[ei[N_EDGES + e]], 1);
}

__global__ void k_dinv() {
    int i = blockIdx.x * blockDim.x + threadIdx.x;
    if (i < N_NODES) g_dinv[i] = rsqrtf((float)(g_cnt[i] + 1));  // +1 self-loop
}

__global__ void k_scan1() {
    __shared__ int s[256];
    int tid = threadIdx.x;
    int i = blockIdx.x * 256 + tid;
    int v = (i < N_NODES) ? g_cnt[i] : 0;
    s[tid] = v;
    __syncthreads();
#pragma unroll
    for (int d = 1; d < 256; d <<= 1) {
        int t = (tid >= d) ? s[tid - d] : 0;
        __syncthreads();
        s[tid] += t;
        __syncthreads();
    }
    if (i < N_NODES) g_off[i] = s[tid] - v;
    if (tid == 255) g_bsum[blockIdx.x] = s[255];
}

__global__ void k_scan2() {
    __shared__ int s[SCAN_NB];
    int tid = threadIdx.x;
    int v = (tid < SCAN_NB) ? g_bsum[tid] : 0;
    if (tid < SCAN_NB) s[tid] = v;
    __syncthreads();
    for (int d = 1; d < SCAN_NB; d <<= 1) {
        int t = (tid >= d && tid < SCAN_NB) ? s[tid - d] : 0;
        __syncthreads();
        if (tid < SCAN_NB) s[tid] += t;
        __syncthreads();
    }
    if (tid < SCAN_NB) g_boff[tid] = s[tid] - v;
}

__global__ void k_scan3() {
    int i = blockIdx.x * blockDim.x + threadIdx.x;
    if (i < N_NODES) {
        int o = g_off[i] + g_boff[i >> 8];
        g_off[i] = o;
        g_cur[i] = o;
    }
    if (i == 0) g_off[N_NODES] = N_EDGES;
}

__global__ void k_scatter(const int* __restrict__ ei) {
    int e = blockIdx.x * blockDim.x + threadIdx.x;
    if (e >= N_EDGES) return;
    int src = ei[e];
    int dst = ei[N_EDGES + e];
    int pos = atomicAdd(&g_cur[dst], 1);
    float norm = g_dinv[src] * g_dinv[dst];
    g_edge[pos] = make_int2(src, __float_as_int(norm));
}

// ---------------- tf32x3 tensor-core GEMM ----------------
__device__ __forceinline__ void tf32_split(float a, uint32_t& hi, uint32_t& lo) {
    uint32_t h;
    asm("cvt.rna.tf32.f32 %0, %1;" : "=r"(h) : "f"(a));
    float l = a - __uint_as_float(h);
    uint32_t lw;
    asm("cvt.rna.tf32.f32 %0, %1;" : "=r"(lw) : "f"(l));
    hi = h; lo = lw;
}

__device__ __forceinline__ void mma_tf32(float* d, const uint32_t* a, const uint32_t* b) {
    asm volatile(
        "mma.sync.aligned.m16n8k8.row.col.f32.tf32.tf32.f32 "
        "{%0,%1,%2,%3},{%4,%5,%6,%7},{%8,%9},{%0,%1,%2,%3};"
        : "+f"(d[0]), "+f"(d[1]), "+f"(d[2]), "+f"(d[3])
        : "r"(a[0]), "r"(a[1]), "r"(a[2]), "r"(a[3]), "r"(b[0]), "r"(b[1]));
}

#define XSTRIDE 20     // floats; (20*r + c) % 32 all-distinct for r0..7, c0..7
#define WSTRIDE 132    // float2s; conflict-free per half-warp

template<bool RELU>
__global__ void __launch_bounds__(256, 2)
k_gemm(const float* __restrict__ X, const float* __restrict__ W,
       float* __restrict__ Out) {
    __shared__ float  sX[128 * XSTRIDE];       // [row][k], 10 KB
    __shared__ float2 sW2[16 * WSTRIDE];       // [k][n] {hi,lo}, 16.5 KB

    int tid  = threadIdx.x;
    int warp = tid >> 5;
    int lane = tid & 31;
    int g    = lane >> 2;      // groupID
    int tg   = lane & 3;       // thread-in-group
    int row0 = blockIdx.x * 128;
    int rb   = warp * 16;      // warp row base within tile

    float acc[16][4];
#pragma unroll
    for (int n = 0; n < 16; n++)
#pragma unroll
        for (int c = 0; c < 4; c++) acc[n][c] = 0.f;

    for (int kk = 0; kk < DIM; kk += 16) {
        // fill X chunk: 128 rows x 16 k  (512 float4, 2 per thread)
#pragma unroll
        for (int i = 0; i < 2; i++) {
            int idx = i * 256 + tid;
            int r = idx >> 2, c4 = (idx & 3) * 4;
            int row = row0 + r;
            float4 v = make_float4(0.f, 0.f, 0.f, 0.f);
            if (row < N_NODES) v = *(const float4*)&X[row * DIM + kk + c4];
            if (RELU) {
                v.x = fmaxf(v.x, 0.f); v.y = fmaxf(v.y, 0.f);
                v.z = fmaxf(v.z, 0.f); v.w = fmaxf(v.w, 0.f);
            }
            *(float4*)&sX[r * XSTRIDE + c4] = v;
        }
        // fill W chunk split into {hi,lo}: 16 k x 128 n  (512 float4 reads -> float2 writes)
#pragma unroll
        for (int i = 0; i < 2; i++) {
            int idx = i * 256 + tid;
            int r = idx >> 5, c4 = (idx & 31) * 4;
            float4 v = *(const float4*)&W[(kk + r) * DIM + c4];
            float vv[4] = {v.x, v.y, v.z, v.w};
#pragma unroll
            for (int j = 0; j < 4; j++) {
                uint32_t h, l;
                tf32_split(vv[j], h, l);
                sW2[r * WSTRIDE + c4 + j] =
                    make_float2(__uint_as_float(h), __uint_as_float(l));
            }
        }
        __syncthreads();

#pragma unroll
        for (int k8 = 0; k8 < 16; k8 += 8) {
            // A fragments (hi/lo) for this warp's 16x8 block
            uint32_t ah[4], al[4];
            tf32_split(sX[(rb + g    ) * XSTRIDE + k8 + tg    ], ah[0], al[0]);
            tf32_split(sX[(rb + g + 8) * XSTRIDE + k8 + tg    ], ah[1], al[1]);
            tf32_split(sX[(rb + g    ) * XSTRIDE + k8 + tg + 4], ah[2], al[2]);
            tf32_split(sX[(rb + g + 8) * XSTRIDE + k8 + tg + 4], ah[3], al[3]);

#pragma unroll
            for (int nt = 0; nt < 16; nt++) {
                float2 p0 = sW2[(k8 + tg    ) * WSTRIDE + nt * 8 + g];
                float2 p1 = sW2[(k8 + tg + 4) * WSTRIDE + nt * 8 + g];
                uint32_t bh[2] = {__float_as_uint(p0.x), __float_as_uint(p1.x)};
                uint32_t bl[2] = {__float_as_uint(p0.y), __float_as_uint(p1.y)};
                mma_tf32(acc[nt], ah, bh);
                mma_tf32(acc[nt], ah, bl);
                mma_tf32(acc[nt], al, bh);
            }
        }
        __syncthreads();
    }

    // epilogue: c0,c1 -> (g, 2tg..2tg+1); c2,c3 -> (g+8, ...)
    int r_lo = row0 + rb + g;
    int r_hi = r_lo + 8;
#pragma unroll
    for (int nt = 0; nt < 16; nt++) {
        int col = nt * 8 + 2 * tg;
        if (r_lo < N_NODES)
            *(float2*)&Out[r_lo * DIM + col] = make_float2(acc[nt][0], acc[nt][1]);
        if (r_hi < N_NODES)
            *(float2*)&Out[r_hi * DIM + col] = make_float2(acc[nt][2], acc[nt][3]);
    }
}

// ---------------- CSR gather aggregation ----------------
__global__ void k_gather(const float* __restrict__ tmp, const float* __restrict__ bias,
                         float* __restrict__ out) {
    int node = (int)((blockIdx.x * (unsigned)blockDim.x + threadIdx.x) >> 5);
    int lane = threadIdx.x & 31;
    if (node >= N_NODES) return;

    int beg = g_off[node];
    int end = g_off[node + 1];
    float dd = g_dinv[node];
    float self = dd * dd;

    float4 v = *(const float4*)&tmp[node * DIM + lane * 4];
    float4 acc = make_float4(v.x * self, v.y * self, v.z * self, v.w * self);

    int e = beg;
    for (; e + 3 < end; e += 4) {
        int2 m0 = g_edge[e + 0];
        int2 m1 = g_edge[e + 1];
        int2 m2 = g_edge[e + 2];
        int2 m3 = g_edge[e + 3];
        float4 v0 = *(const float4*)&tmp[m0.x * DIM + lane * 4];
        float4 v1 = *(const float4*)&tmp[m1.x * DIM + lane * 4];
        float4 v2 = *(const float4*)&tmp[m2.x * DIM + lane * 4];
        float4 v3 = *(const float4*)&tmp[m3.x * DIM + lane * 4];
        float n0 = __int_as_float(m0.y), n1 = __int_as_float(m1.y);
        float n2 = __int_as_float(m2.y), n3 = __int_as_float(m3.y);
        acc.x += v0.x * n0 + v1.x * n1 + v2.x * n2 + v3.x * n3;
        acc.y += v0.y * n0 + v1.y * n1 + v2.y * n2 + v3.y * n3;
        acc.z += v0.z * n0 + v1.z * n1 + v2.z * n2 + v3.z * n3;
        acc.w += v0.w * n0 + v1.w * n1 + v2.w * n2 + v3.w * n3;
    }
    for (; e < end; e++) {
        int2 m0 = g_edge[e];
        float n0 = __int_as_float(m0.y);
        float4 v0 = *(const float4*)&tmp[m0.x * DIM + lane * 4];
        acc.x += v0.x * n0; acc.y += v0.y * n0;
        acc.z += v0.z * n0; acc.w += v0.w * n0;
    }

    float4 bb = *(const float4*)&bias[lane * 4];
    acc.x += bb.x; acc.y += bb.y; acc.z += bb.z; acc.w += bb.w;
    *(float4*)&out[node * DIM + lane * 4] = acc;
}

// ---------------- launch ----------------
extern "C" void kernel_launch(void* const* d_in, const int* in_sizes, int n_in,
                              void* d_out, int out_size) {
    const float* x  = (const float*)d_in[0];
    const int*   ei = (const int*)d_in[1];
    const float* W1 = (const float*)d_in[2];
    const float* b1 = (const float*)d_in[3];
    const float* W2 = (const float*)d_in[4];
    const float* b2 = (const float*)d_in[5];
    float* out = (float*)d_out;

    float* tmp_p; cudaGetSymbolAddress((void**)&tmp_p, g_tmp);
    float* h_p;   cudaGetSymbolAddress((void**)&h_p,   g_h);

    int nthr = 256;
    int nb_nodes  = (N_NODES + nthr - 1) / nthr;
    int nb_edges  = (N_EDGES + nthr - 1) / nthr;
    int nb_gemm   = (N_NODES + 127) / 128;
    int nb_gather = (N_NODES * 32 + nthr - 1) / nthr;

    // CSR build (by destination) + normalization
    k_zero_cnt<<<nb_nodes, nthr>>>();
    k_hist<<<nb_edges, nthr>>>(ei);
    k_dinv<<<nb_nodes, nthr>>>();
    k_scan1<<<SCAN_NB, 256>>>();
    k_scan2<<<1, 256>>>();
    k_scan3<<<SCAN_NB, 256>>>();
    k_scatter<<<nb_edges, nthr>>>(ei);

    // layer 1
    k_gemm<false><<<nb_gemm, nthr>>>(x, W1, tmp_p);
    k_gather<<<nb_gather, nthr>>>(tmp_p, b1, h_p);

    // layer 2
    k_gemm<true><<<nb_gemm, nthr>>>(h_p, W2, tmp_p);
    k_gather<<<nb_gather, nthr>>>(tmp_p, b2, out);
}